// round 11
// baseline (speedup 1.0000x reference)
#include <cuda_runtime.h>
#include <cuda_fp16.h>
#include <mma.h>
#include <math.h>

using namespace nvcuda;

#define NN   50000
#define DH   128
#define DOUT 57
#define TOTE (800000 + NN)

// -------- scratch (__device__ globals; zero-initialized at load) --------
__device__ uint2  g_hh[NN * 32];   // h in fp16: [N][32] x (2 half2)
__device__ float4 g_t4[NN * 32];   // aggregation output [N,128] fp32
__device__ float  g_as[NN];        // alpha_src per node
__device__ float  g_ad[NN];        // alpha_dst per node
__device__ int    g_deg[NN];       // zero-init; reset to 0 by k_scan each replay
__device__ int    g_off[NN + 1];
__device__ int    g_cur[NN];
__device__ int    g_srcs[TOTE];    // CSR (by dst): src node per edge

// ---------------- fp16x2 <-> fp32 helpers ----------------
__device__ __forceinline__ unsigned int f2_to_h2(float lo, float hi) {
    unsigned int r;
    asm("cvt.rn.f16x2.f32 %0, %2, %1;" : "=r"(r) : "f"(lo), "f"(hi));
    return r;
}
__device__ __forceinline__ float2 h2_to_f2(unsigned int u) {
    __half2 h = *reinterpret_cast<__half2*>(&u);
    return __half22float2(h);
}

// ============================ CSR build (3 kernels) ============================
__global__ void k_count(const int* __restrict__ ei, int E) {
    int e4 = blockIdx.x * blockDim.x + threadIdx.x;
    if (e4 * 4 < E) {
        int4 d = ((const int4*)(ei + E))[e4];
        if (d.x >= 0 && d.x < NN) atomicAdd(&g_deg[d.x], 1);
        if (d.y >= 0 && d.y < NN) atomicAdd(&g_deg[d.y], 1);
        if (d.z >= 0 && d.z < NN) atomicAdd(&g_deg[d.z], 1);
        if (d.w >= 0 && d.w < NN) atomicAdd(&g_deg[d.w], 1);
    }
}

__global__ void k_scan() {
    __shared__ int sums[1024];
    const int n = NN;
    int tid = threadIdx.x;
    const int chunk = (n + 1023) / 1024;
    int base = tid * chunk;
    int s = 0;
    for (int i = 0; i < chunk; ++i) {
        int idx = base + i;
        if (idx < n) s += g_deg[idx] + 1;
    }
    sums[tid] = s;
    __syncthreads();
    for (int d = 1; d < 1024; d <<= 1) {
        int v = (tid >= d) ? sums[tid - d] : 0;
        __syncthreads();
        sums[tid] += v;
        __syncthreads();
    }
    int run = (tid == 0) ? 0 : sums[tid - 1];
    for (int i = 0; i < chunk; ++i) {
        int idx = base + i;
        if (idx < n) {
            g_off[idx] = run;
            g_srcs[run] = idx;      // self loop in slot 0
            g_cur[idx] = run + 1;
            run += g_deg[idx] + 1;
            g_deg[idx] = 0;         // reset for next replay
        }
    }
    if (tid == 1023) g_off[n] = sums[1023];
}

__global__ void k_scatter(const int* __restrict__ ei, int E) {
    int e4 = blockIdx.x * blockDim.x + threadIdx.x;
    if (e4 * 4 < E) {
        int4 sv = ((const int4*)ei)[e4];
        int4 dv = ((const int4*)(ei + E))[e4];
        int ss[4] = {sv.x, sv.y, sv.z, sv.w};
        int dd[4] = {dv.x, dv.y, dv.z, dv.w};
#pragma unroll
        for (int k = 0; k < 4; ++k) {
            int d = dd[k], s = ss[k];
            if (d >= 0 && d < NN && s >= 0 && s < NN) {
                int p = atomicAdd(&g_cur[d], 1);
                if (p >= 0 && p < TOTE) g_srcs[p] = s;
            }
        }
    }
}

// ============================ GEMM: wmma tf32 tensor cores ============================
// Block 64 rows x 128 cols, 8 warps; warp (wm,wn) computes rows wm*16.., cols wn*64..
// A staged (+relu, tf32-rounded) in smem; W staged in 32-k quarters (tf32-rounded).
// C written back through smem; fused epilogue as before.
template <int MODE>
__global__ void __launch_bounds__(256) gemm_kernel(const float4* __restrict__ Aext,
                            const float* __restrict__ W,
                            const float* __restrict__ avs,
                            const float* __restrict__ avd,
                            const float* __restrict__ bias,
                            float* __restrict__ Cext) {
    constexpr int  Wn   = (MODE == 2) ? DOUT : DH;
    constexpr bool RELU = (MODE == 1);
    __shared__ float As[64 * 128];    // 32 KB: A tile, then reused as C tile
    __shared__ float Ws[32 * 128];    // 16 KB: W quarter [32 k][128 cols]

    const float4* A = (MODE == 0) ? Aext : g_t4;

    int tid = threadIdx.x;            // 256 threads = 8 warps
    int tx = tid & 31;
    int wid = tid >> 5;
    int wm = wid >> 1;                // 0..3: row group of 16
    int wn = wid & 1;                 // 0..1: col group of 64
    int rowBase = blockIdx.x * 64;
    int rmax = NN - rowBase;

    // stage A tile (tf32-rounded, relu, zero-pad invalid rows)
    for (int i = tid; i < 64 * 32; i += 256) {
        int r = i >> 5;
        float4 a = make_float4(0.f, 0.f, 0.f, 0.f);
        if (r < rmax) a = A[rowBase * 32 + i];
        if (RELU) {
            a.x = fmaxf(a.x, 0.f); a.y = fmaxf(a.y, 0.f);
            a.z = fmaxf(a.z, 0.f); a.w = fmaxf(a.w, 0.f);
        }
        a.x = wmma::__float_to_tf32(a.x); a.y = wmma::__float_to_tf32(a.y);
        a.z = wmma::__float_to_tf32(a.z); a.w = wmma::__float_to_tf32(a.w);
        ((float4*)As)[i] = a;
    }

    wmma::fragment<wmma::accumulator, 16, 16, 8, float> c[4];
#pragma unroll
    for (int n = 0; n < 4; ++n) wmma::fill_fragment(c[n], 0.f);

    for (int q = 0; q < 4; ++q) {
        __syncthreads();              // Ws reuse (+ q==0: As ready)
        for (int i = tid; i < 32 * 128; i += 256) {
            int k = i >> 7, cc = i & 127;
            float v = (cc < Wn) ? W[(q * 32 + k) * Wn + cc] : 0.f;
            Ws[i] = wmma::__float_to_tf32(v);
        }
        __syncthreads();

#pragma unroll
        for (int k8 = 0; k8 < 4; ++k8) {
            wmma::fragment<wmma::matrix_a, 16, 16, 8, wmma::precision::tf32, wmma::row_major> af;
            wmma::load_matrix_sync(af, &As[(wm * 16) * 128 + q * 32 + k8 * 8], 128);
#pragma unroll
            for (int n = 0; n < 4; ++n) {
                wmma::fragment<wmma::matrix_b, 16, 16, 8, wmma::precision::tf32, wmma::row_major> bf;
                wmma::load_matrix_sync(bf, &Ws[(k8 * 8) * 128 + wn * 64 + n * 16], 128);
                wmma::mma_sync(c[n], af, bf, c[n]);
            }
        }
    }

    // write C back to smem (reuse As)
    __syncthreads();
#pragma unroll
    for (int n = 0; n < 4; ++n)
        wmma::store_matrix_sync(&As[(wm * 16) * 128 + wn * 64 + n * 16], c[n], 128, wmma::mem_row_major);
    __syncthreads();

    // fused epilogue: warp wid handles rows wid*8..wid*8+7; lane tx owns cols 4tx..4tx+3
    int ty = wid;
    if (MODE < 2) {
        float as0 = avs[4 * tx + 0], as1 = avs[4 * tx + 1], as2 = avs[4 * tx + 2], as3 = avs[4 * tx + 3];
        float ad0 = avd[4 * tx + 0], ad1 = avd[4 * tx + 1], ad2 = avd[4 * tx + 2], ad3 = avd[4 * tx + 3];
#pragma unroll
        for (int i = 0; i < 8; ++i) {
            int row = rowBase + ty * 8 + i;
            float4 acc = ((float4*)As)[(ty * 8 + i) * 32 + tx];
            float ps = acc.x * as0 + acc.y * as1 + acc.z * as2 + acc.w * as3;
            float pd = acc.x * ad0 + acc.y * ad1 + acc.z * ad2 + acc.w * ad3;
#pragma unroll
            for (int o = 16; o; o >>= 1) {
                ps += __shfl_xor_sync(0xffffffffu, ps, o);
                pd += __shfl_xor_sync(0xffffffffu, pd, o);
            }
            if (row < NN) {
                g_hh[row * 32 + tx] = make_uint2(f2_to_h2(acc.x, acc.y),
                                                 f2_to_h2(acc.z, acc.w));
                if (tx == 0) { g_as[row] = ps; g_ad[row] = pd; }
            }
        }
    } else {
#pragma unroll
        for (int i = 0; i < 8; ++i) {
            int row = rowBase + ty * 8 + i;
            if (row < NN) {
                float4 acc = ((float4*)As)[(ty * 8 + i) * 32 + tx];
                float v[4] = {acc.x, acc.y, acc.z, acc.w};
#pragma unroll
                for (int j = 0; j < 4; ++j) {
                    int col = 4 * tx + j;
                    if (col < DOUT) Cext[row * DOUT + col] = v[j] + bias[col];
                }
            }
        }
    }
}

// ==================== segment softmax + aggregation (fp16 h gather) ====================
__global__ void __launch_bounds__(256) agg_kernel(const float* __restrict__ bias) {
    int w = (blockIdx.x * blockDim.x + threadIdx.x) >> 5;
    if (w >= NN) return;
    int lane = threadIdx.x & 31;
    int beg = g_off[w], end = g_off[w + 1];
    float adn = g_ad[w];

    float4 acc0 = make_float4(0.f, 0.f, 0.f, 0.f);
    float4 acc1 = make_float4(0.f, 0.f, 0.f, 0.f);
    float den = 0.f;

    for (int b = beg; b < end; b += 32) {
        int j = b + lane;
        int s = 0; float ex = 0.f;
        if (j < end) {
            s = g_srcs[j];
            float e = g_as[s] + adn;
            e = (e > 0.f) ? e : 0.2f * e;
            ex = __expf(e);
        }
        den += ex;
        int cnt = min(32, end - b);
        int jj = 0;
        for (; jj + 2 <= cnt; jj += 2) {
            int   s0 = __shfl_sync(0xffffffffu, s,  jj);
            int   s1 = __shfl_sync(0xffffffffu, s,  jj + 1);
            float w0 = __shfl_sync(0xffffffffu, ex, jj);
            float w1 = __shfl_sync(0xffffffffu, ex, jj + 1);
            uint2 u0 = g_hh[s0 * 32 + lane];
            uint2 u1 = g_hh[s1 * 32 + lane];
            float2 f0a = h2_to_f2(u0.x);
            float2 f0b = h2_to_f2(u0.y);
            float2 f1a = h2_to_f2(u1.x);
            float2 f1b = h2_to_f2(u1.y);
            acc0.x += w0 * f0a.x; acc0.y += w0 * f0a.y; acc0.z += w0 * f0b.x; acc0.w += w0 * f0b.y;
            acc1.x += w1 * f1a.x; acc1.y += w1 * f1a.y; acc1.z += w1 * f1b.x; acc1.w += w1 * f1b.y;
        }
        if (jj < cnt) {
            int   s0 = __shfl_sync(0xffffffffu, s,  jj);
            float w0 = __shfl_sync(0xffffffffu, ex, jj);
            uint2 u0 = g_hh[s0 * 32 + lane];
            float2 f0a = h2_to_f2(u0.x);
            float2 f0b = h2_to_f2(u0.y);
            acc0.x += w0 * f0a.x; acc0.y += w0 * f0a.y; acc0.z += w0 * f0b.x; acc0.w += w0 * f0b.y;
        }
    }
#pragma unroll
    for (int o = 16; o; o >>= 1) den += __shfl_xor_sync(0xffffffffu, den, o);
    float inv = 1.0f / den;

    float b0 = bias[4 * lane + 0], b1 = bias[4 * lane + 1];
    float b2 = bias[4 * lane + 2], b3 = bias[4 * lane + 3];
    g_t4[w * 32 + lane] = make_float4((acc0.x + acc1.x) * inv + b0,
                                      (acc0.y + acc1.y) * inv + b1,
                                      (acc0.z + acc1.z) * inv + b2,
                                      (acc0.w + acc1.w) * inv + b3);
}

// ============================ launch ============================
extern "C" void kernel_launch(void* const* d_in, const int* in_sizes, int n_in,
                              void* d_out, int out_size) {
    const float* x   = (const float*)d_in[0];
    const int*   ei  = (const int*)d_in[1];     // int32 (JAX x64-disabled)
    const float* W1  = (const float*)d_in[2];
    const float* a1s = (const float*)d_in[3];
    const float* a1d = (const float*)d_in[4];
    const float* b1  = (const float*)d_in[5];
    const float* W2  = (const float*)d_in[6];
    const float* a2s = (const float*)d_in[7];
    const float* a2d = (const float*)d_in[8];
    const float* b2  = (const float*)d_in[9];
    const float* fcw = (const float*)d_in[10];
    const float* fcb = (const float*)d_in[11];
    float*       out = (float*)d_out;
    int E = in_sizes[1] / 2;
    int E4 = (E + 3) / 4;

    int gemm_blocks = (NN + 63) / 64;
    int agg_blocks  = (NN * 32 + 255) / 256;

    k_count<<<(E4 + 255) / 256, 256>>>(ei, E);
    k_scan<<<1, 1024>>>();
    k_scatter<<<(E4 + 255) / 256, 256>>>(ei, E);

    // layer 1 (gemm0 = profiled slot)
    gemm_kernel<0><<<gemm_blocks, 256>>>((const float4*)x, W1, a1s, a1d, nullptr, nullptr);
    agg_kernel<<<agg_blocks, 256>>>(b1);
    // layer 2
    gemm_kernel<1><<<gemm_blocks, 256>>>(nullptr, W2, a2s, a2d, nullptr, nullptr);
    agg_kernel<<<agg_blocks, 256>>>(b2);
    // output head
    gemm_kernel<2><<<gemm_blocks, 256>>>(nullptr, fcw, nullptr, nullptr, fcb, out);
}

// round 12
// speedup vs baseline: 1.0540x; 1.0540x over previous
#include <cuda_runtime.h>
#include <cuda_fp16.h>
#include <math.h>

#define NN   50000
#define DH   128
#define DOUT 57
#define TOTE (800000 + NN)

// -------- scratch (__device__ globals; zero-initialized at load) --------
__device__ uint2  g_hh[NN * 32];   // h in fp16: [N][32] x (2 half2)
__device__ float4 g_t4[NN * 32];   // aggregation output [N,128] fp32
__device__ float  g_as[NN];        // alpha_src per node
__device__ float  g_ad[NN];        // alpha_dst per node
__device__ int    g_deg[NN];       // zero-init; reset to 0 by k_scan each replay
__device__ int    g_off[NN + 1];
__device__ int    g_cur[NN];
__device__ int    g_srcs[TOTE];    // CSR (by dst): src node per edge

// ---------------- f32x2 packed-FMA helpers (sm_103a) ----------------
__device__ __forceinline__ unsigned long long pack2(float v) {
    unsigned long long r;
    asm("mov.b64 %0, {%1, %1};" : "=l"(r) : "f"(v));
    return r;
}
__device__ __forceinline__ void fma2(unsigned long long& d,
                                     unsigned long long a, unsigned long long b) {
    asm("fma.rn.f32x2 %0, %1, %2, %0;" : "+l"(d) : "l"(a), "l"(b));
}
__device__ __forceinline__ float2 unpack2(unsigned long long v) {
    float x, y;
    asm("mov.b64 {%0, %1}, %2;" : "=f"(x), "=f"(y) : "l"(v));
    return make_float2(x, y);
}

// ---------------- fp16x2 <-> fp32 helpers ----------------
__device__ __forceinline__ unsigned int f2_to_h2(float lo, float hi) {
    unsigned int r;
    asm("cvt.rn.f16x2.f32 %0, %2, %1;" : "=r"(r) : "f"(lo), "f"(hi));
    return r;
}
__device__ __forceinline__ float2 h2_to_f2(unsigned int u) {
    __half2 h = *reinterpret_cast<__half2*>(&u);
    return __half22float2(h);
}

// ============================ CSR build (3 kernels) ============================
__global__ void k_count(const int* __restrict__ ei, int E) {
    int e4 = blockIdx.x * blockDim.x + threadIdx.x;
    if (e4 * 4 < E) {
        int4 d = ((const int4*)(ei + E))[e4];
        if (d.x >= 0 && d.x < NN) atomicAdd(&g_deg[d.x], 1);
        if (d.y >= 0 && d.y < NN) atomicAdd(&g_deg[d.y], 1);
        if (d.z >= 0 && d.z < NN) atomicAdd(&g_deg[d.z], 1);
        if (d.w >= 0 && d.w < NN) atomicAdd(&g_deg[d.w], 1);
    }
}

__global__ void k_scan() {
    __shared__ int sums[1024];
    const int n = NN;
    int tid = threadIdx.x;
    const int chunk = (n + 1023) / 1024;
    int base = tid * chunk;
    int s = 0;
    for (int i = 0; i < chunk; ++i) {
        int idx = base + i;
        if (idx < n) s += g_deg[idx] + 1;
    }
    sums[tid] = s;
    __syncthreads();
    for (int d = 1; d < 1024; d <<= 1) {
        int v = (tid >= d) ? sums[tid - d] : 0;
        __syncthreads();
        sums[tid] += v;
        __syncthreads();
    }
    int run = (tid == 0) ? 0 : sums[tid - 1];
    for (int i = 0; i < chunk; ++i) {
        int idx = base + i;
        if (idx < n) {
            g_off[idx] = run;
            g_srcs[run] = idx;      // self loop in slot 0
            g_cur[idx] = run + 1;
            run += g_deg[idx] + 1;
            g_deg[idx] = 0;         // reset for next replay
        }
    }
    if (tid == 1023) g_off[n] = sums[1023];
}

__global__ void k_scatter(const int* __restrict__ ei, int E) {
    int e4 = blockIdx.x * blockDim.x + threadIdx.x;
    if (e4 * 4 < E) {
        int4 sv = ((const int4*)ei)[e4];
        int4 dv = ((const int4*)(ei + E))[e4];
        int ss[4] = {sv.x, sv.y, sv.z, sv.w};
        int dd[4] = {dv.x, dv.y, dv.z, dv.w};
#pragma unroll
        for (int k = 0; k < 4; ++k) {
            int d = dd[k], s = ss[k];
            if (d >= 0 && d < NN && s >= 0 && s < NN) {
                int p = atomicAdd(&g_cur[d], 1);
                if (p >= 0 && p < TOTE) g_srcs[p] = s;
            }
        }
    }
}

// ============================ GEMM (R10: smem A-tile, broadcast A, f32x2) ============================
template <int MODE>
__global__ void __launch_bounds__(256) gemm_kernel(const float4* __restrict__ Aext,
                            const float* __restrict__ W,
                            const float* __restrict__ avs,
                            const float* __restrict__ avd,
                            const float* __restrict__ bias,
                            float* __restrict__ Cext) {
    constexpr int  Wn   = (MODE == 2) ? DOUT : DH;
    constexpr bool RELU = (MODE == 1);
    __shared__ float4     As[64 * 32];    // 32 KB A tile [64 rows][32 float4]
    __shared__ ulonglong2 Ws2[32 * 32];   // 16 KB W quarter [32 k][128 cols]

    const float4* A = (MODE == 0) ? Aext : g_t4;

    int tid = threadIdx.x;                // 256 threads
    int tx = tid & 31, ty = tid >> 5;
    int rowBase = blockIdx.x * 64;
    int rmax = NN - rowBase;

    for (int i = tid; i < 64 * 32; i += 256) {
        int r = i >> 5;
        float4 a = make_float4(0.f, 0.f, 0.f, 0.f);
        if (r < rmax) a = A[rowBase * 32 + i];
        if (RELU) {
            a.x = fmaxf(a.x, 0.f); a.y = fmaxf(a.y, 0.f);
            a.z = fmaxf(a.z, 0.f); a.w = fmaxf(a.w, 0.f);
        }
        As[i] = a;
    }

    unsigned long long accL[8], accH[8];
#pragma unroll
    for (int i = 0; i < 8; ++i) { accL[i] = 0ull; accH[i] = 0ull; }

    float* Wsf = (float*)Ws2;
    for (int q = 0; q < 4; ++q) {
        __syncthreads();
        for (int i = tid; i < 32 * DH; i += 256) {
            int k = i >> 7, c = i & 127;
            Wsf[i] = (c < Wn) ? W[(q * 32 + k) * Wn + c] : 0.f;
        }
        __syncthreads();

#pragma unroll 2
        for (int k4 = 0; k4 < 8; ++k4) {
            ulonglong2 w0 = Ws2[(k4 * 4 + 0) * 32 + tx];
            ulonglong2 w1 = Ws2[(k4 * 4 + 1) * 32 + tx];
            ulonglong2 w2 = Ws2[(k4 * 4 + 2) * 32 + tx];
            ulonglong2 w3 = Ws2[(k4 * 4 + 3) * 32 + tx];
#pragma unroll
            for (int i = 0; i < 8; ++i) {
                float4 a = As[(ty * 8 + i) * 32 + q * 8 + k4];
                unsigned long long ax = pack2(a.x), ay = pack2(a.y);
                unsigned long long az = pack2(a.z), aw = pack2(a.w);
                fma2(accL[i], ax, w0.x); fma2(accH[i], ax, w0.y);
                fma2(accL[i], ay, w1.x); fma2(accH[i], ay, w1.y);
                fma2(accL[i], az, w2.x); fma2(accH[i], az, w2.y);
                fma2(accL[i], aw, w3.x); fma2(accH[i], aw, w3.y);
            }
        }
    }

    if (MODE < 2) {
        float as0 = avs[4 * tx + 0], as1 = avs[4 * tx + 1], as2 = avs[4 * tx + 2], as3 = avs[4 * tx + 3];
        float ad0 = avd[4 * tx + 0], ad1 = avd[4 * tx + 1], ad2 = avd[4 * tx + 2], ad3 = avd[4 * tx + 3];
#pragma unroll
        for (int i = 0; i < 8; ++i) {
            int row = rowBase + ty * 8 + i;
            float2 lo = unpack2(accL[i]), hi = unpack2(accH[i]);
            float4 acc = make_float4(lo.x, lo.y, hi.x, hi.y);
            float ps = acc.x * as0 + acc.y * as1 + acc.z * as2 + acc.w * as3;
            float pd = acc.x * ad0 + acc.y * ad1 + acc.z * ad2 + acc.w * ad3;
#pragma unroll
            for (int o = 16; o; o >>= 1) {
                ps += __shfl_xor_sync(0xffffffffu, ps, o);
                pd += __shfl_xor_sync(0xffffffffu, pd, o);
            }
            if (row < NN) {
                g_hh[row * 32 + tx] = make_uint2(f2_to_h2(acc.x, acc.y),
                                                 f2_to_h2(acc.z, acc.w));
                if (tx == 0) { g_as[row] = ps; g_ad[row] = pd; }
            }
        }
    } else {
#pragma unroll
        for (int i = 0; i < 8; ++i) {
            int row = rowBase + ty * 8 + i;
            if (row < NN) {
                float2 lo = unpack2(accL[i]), hi = unpack2(accH[i]);
                float v[4] = {lo.x, lo.y, hi.x, hi.y};
#pragma unroll
                for (int j = 0; j < 4; ++j) {
                    int col = 4 * tx + j;
                    if (col < DOUT) Cext[row * DOUT + col] = v[j] + bias[col];
                }
            }
        }
    }
}

// ==================== segment softmax + aggregation (fp16 h, 4-way MLP) ====================
__global__ void __launch_bounds__(256) agg_kernel(const float* __restrict__ bias) {
    int w = (blockIdx.x * blockDim.x + threadIdx.x) >> 5;
    if (w >= NN) return;
    int lane = threadIdx.x & 31;
    int beg = g_off[w], end = g_off[w + 1];
    float adn = g_ad[w];

    float4 a0 = make_float4(0.f, 0.f, 0.f, 0.f);
    float4 a1 = make_float4(0.f, 0.f, 0.f, 0.f);
    float4 a2 = make_float4(0.f, 0.f, 0.f, 0.f);
    float4 a3 = make_float4(0.f, 0.f, 0.f, 0.f);
    float den = 0.f;

    for (int b = beg; b < end; b += 32) {
        int j = b + lane;
        int s = 0; float ex = 0.f;
        if (j < end) {
            s = g_srcs[j];
            float e = g_as[s] + adn;
            e = (e > 0.f) ? e : 0.2f * e;
            ex = __expf(e);
        }
        den += ex;
        int cnt = min(32, end - b);
        int jj = 0;
        for (; jj + 4 <= cnt; jj += 4) {
            int   s0 = __shfl_sync(0xffffffffu, s,  jj);
            int   s1 = __shfl_sync(0xffffffffu, s,  jj + 1);
            int   s2 = __shfl_sync(0xffffffffu, s,  jj + 2);
            int   s3 = __shfl_sync(0xffffffffu, s,  jj + 3);
            float w0 = __shfl_sync(0xffffffffu, ex, jj);
            float w1 = __shfl_sync(0xffffffffu, ex, jj + 1);
            float w2 = __shfl_sync(0xffffffffu, ex, jj + 2);
            float w3 = __shfl_sync(0xffffffffu, ex, jj + 3);
            uint2 u0 = g_hh[s0 * 32 + lane];
            uint2 u1 = g_hh[s1 * 32 + lane];
            uint2 u2 = g_hh[s2 * 32 + lane];
            uint2 u3 = g_hh[s3 * 32 + lane];
            float2 f0a = h2_to_f2(u0.x), f0b = h2_to_f2(u0.y);
            float2 f1a = h2_to_f2(u1.x), f1b = h2_to_f2(u1.y);
            float2 f2a = h2_to_f2(u2.x), f2b = h2_to_f2(u2.y);
            float2 f3a = h2_to_f2(u3.x), f3b = h2_to_f2(u3.y);
            a0.x += w0 * f0a.x; a0.y += w0 * f0a.y; a0.z += w0 * f0b.x; a0.w += w0 * f0b.y;
            a1.x += w1 * f1a.x; a1.y += w1 * f1a.y; a1.z += w1 * f1b.x; a1.w += w1 * f1b.y;
            a2.x += w2 * f2a.x; a2.y += w2 * f2a.y; a2.z += w2 * f2b.x; a2.w += w2 * f2b.y;
            a3.x += w3 * f3a.x; a3.y += w3 * f3a.y; a3.z += w3 * f3b.x; a3.w += w3 * f3b.y;
        }
        for (; jj < cnt; ++jj) {
            int   s0 = __shfl_sync(0xffffffffu, s,  jj);
            float w0 = __shfl_sync(0xffffffffu, ex, jj);
            uint2 u0 = g_hh[s0 * 32 + lane];
            float2 f0a = h2_to_f2(u0.x), f0b = h2_to_f2(u0.y);
            a0.x += w0 * f0a.x; a0.y += w0 * f0a.y; a0.z += w0 * f0b.x; a0.w += w0 * f0b.y;
        }
    }
#pragma unroll
    for (int o = 16; o; o >>= 1) den += __shfl_xor_sync(0xffffffffu, den, o);
    float inv = 1.0f / den;

    float b0 = bias[4 * lane + 0], b1 = bias[4 * lane + 1];
    float b2 = bias[4 * lane + 2], b3 = bias[4 * lane + 3];
    g_t4[w * 32 + lane] = make_float4((a0.x + a1.x + a2.x + a3.x) * inv + b0,
                                      (a0.y + a1.y + a2.y + a3.y) * inv + b1,
                                      (a0.z + a1.z + a2.z + a3.z) * inv + b2,
                                      (a0.w + a1.w + a2.w + a3.w) * inv + b3);
}

// ============================ launch ============================
extern "C" void kernel_launch(void* const* d_in, const int* in_sizes, int n_in,
                              void* d_out, int out_size) {
    const float* x   = (const float*)d_in[0];
    const int*   ei  = (const int*)d_in[1];     // int32 (JAX x64-disabled)
    const float* W1  = (const float*)d_in[2];
    const float* a1s = (const float*)d_in[3];
    const float* a1d = (const float*)d_in[4];
    const float* b1  = (const float*)d_in[5];
    const float* W2  = (const float*)d_in[6];
    const float* a2s = (const float*)d_in[7];
    const float* a2d = (const float*)d_in[8];
    const float* b2  = (const float*)d_in[9];
    const float* fcw = (const float*)d_in[10];
    const float* fcb = (const float*)d_in[11];
    float*       out = (float*)d_out;
    int E = in_sizes[1] / 2;
    int E4 = (E + 3) / 4;

    int gemm_blocks = (NN + 63) / 64;
    int agg_blocks  = (NN * 32 + 255) / 256;

    k_count<<<(E4 + 255) / 256, 256>>>(ei, E);
    k_scan<<<1, 1024>>>();
    k_scatter<<<(E4 + 255) / 256, 256>>>(ei, E);

    // layer 1 (gemm0 = profiled slot)
    gemm_kernel<0><<<gemm_blocks, 256>>>((const float4*)x, W1, a1s, a1d, nullptr, nullptr);
    agg_kernel<<<agg_blocks, 256>>>(b1);
    // layer 2
    gemm_kernel<1><<<gemm_blocks, 256>>>(nullptr, W2, a2s, a2d, nullptr, nullptr);
    agg_kernel<<<agg_blocks, 256>>>(b2);
    // output head
    gemm_kernel<2><<<gemm_blocks, 256>>>(nullptr, fcw, nullptr, nullptr, fcb, out);
}

// round 13
// speedup vs baseline: 1.1399x; 1.0814x over previous
#include <cuda_runtime.h>
#include <cuda_fp16.h>
#include <math.h>

#define NN   50000
#define DH   128
#define DOUT 57
#define TOTE (800000 + NN)

// -------- scratch (__device__ globals; zero-initialized at load) --------
__device__ uint2  g_hh[NN * 32];   // h in fp16: [N][32] x (2 half2)
__device__ float4 g_t4[NN * 32];   // aggregation output [N,128] fp32
__device__ float  g_as[NN];        // alpha_src per node
__device__ float  g_ad[NN];        // alpha_dst per node
__device__ int    g_deg[NN];       // zero-init; reset to 0 by k_scan each replay
__device__ int    g_off[NN + 1];
__device__ int    g_cur[NN];
__device__ int    g_srcs[TOTE];    // CSR (by dst): src node per edge

// ---------------- f32x2 packed-FMA helpers (sm_103a) ----------------
__device__ __forceinline__ unsigned long long pack2(float v) {
    unsigned long long r;
    asm("mov.b64 %0, {%1, %1};" : "=l"(r) : "f"(v));
    return r;
}
__device__ __forceinline__ void fma2(unsigned long long& d,
                                     unsigned long long a, unsigned long long b) {
    asm("fma.rn.f32x2 %0, %1, %2, %0;" : "+l"(d) : "l"(a), "l"(b));
}
__device__ __forceinline__ float2 unpack2(unsigned long long v) {
    float x, y;
    asm("mov.b64 {%0, %1}, %2;" : "=f"(x), "=f"(y) : "l"(v));
    return make_float2(x, y);
}

// ---------------- fp16x2 <-> fp32 helpers ----------------
__device__ __forceinline__ unsigned int f2_to_h2(float lo, float hi) {
    unsigned int r;
    asm("cvt.rn.f16x2.f32 %0, %2, %1;" : "=r"(r) : "f"(lo), "f"(hi));
    return r;
}
__device__ __forceinline__ float2 h2_to_f2(unsigned int u) {
    __half2 h = *reinterpret_cast<__half2*>(&u);
    return __half22float2(h);
}

// ---------------- cp.async helpers ----------------
__device__ __forceinline__ void cp_async16(void* smem_dst, const void* gmem_src) {
    unsigned int d = (unsigned int)__cvta_generic_to_shared(smem_dst);
    asm volatile("cp.async.cg.shared.global [%0], [%1], 16;" :: "r"(d), "l"(gmem_src));
}
__device__ __forceinline__ void cp_async_commit() {
    asm volatile("cp.async.commit_group;" ::: "memory");
}
__device__ __forceinline__ void cp_async_wait_all() {
    asm volatile("cp.async.wait_group 0;" ::: "memory");
}

// ============================ CSR build (3 kernels) ============================
__global__ void k_count(const int* __restrict__ ei, int E) {
    int e4 = blockIdx.x * blockDim.x + threadIdx.x;
    if (e4 * 4 < E) {
        int4 d = ((const int4*)(ei + E))[e4];
        if (d.x >= 0 && d.x < NN) atomicAdd(&g_deg[d.x], 1);
        if (d.y >= 0 && d.y < NN) atomicAdd(&g_deg[d.y], 1);
        if (d.z >= 0 && d.z < NN) atomicAdd(&g_deg[d.z], 1);
        if (d.w >= 0 && d.w < NN) atomicAdd(&g_deg[d.w], 1);
    }
}

__global__ void k_scan() {
    __shared__ int sums[1024];
    const int n = NN;
    int tid = threadIdx.x;
    const int chunk = (n + 1023) / 1024;
    int base = tid * chunk;
    int s = 0;
    for (int i = 0; i < chunk; ++i) {
        int idx = base + i;
        if (idx < n) s += g_deg[idx] + 1;
    }
    sums[tid] = s;
    __syncthreads();
    for (int d = 1; d < 1024; d <<= 1) {
        int v = (tid >= d) ? sums[tid - d] : 0;
        __syncthreads();
        sums[tid] += v;
        __syncthreads();
    }
    int run = (tid == 0) ? 0 : sums[tid - 1];
    for (int i = 0; i < chunk; ++i) {
        int idx = base + i;
        if (idx < n) {
            g_off[idx] = run;
            g_srcs[run] = idx;      // self loop in slot 0
            g_cur[idx] = run + 1;
            run += g_deg[idx] + 1;
            g_deg[idx] = 0;         // reset for next replay
        }
    }
    if (tid == 1023) g_off[n] = sums[1023];
}

__global__ void k_scatter(const int* __restrict__ ei, int E) {
    int e4 = blockIdx.x * blockDim.x + threadIdx.x;
    if (e4 * 4 < E) {
        int4 sv = ((const int4*)ei)[e4];
        int4 dv = ((const int4*)(ei + E))[e4];
        int ss[4] = {sv.x, sv.y, sv.z, sv.w};
        int dd[4] = {dv.x, dv.y, dv.z, dv.w};
#pragma unroll
        for (int k = 0; k < 4; ++k) {
            int d = dd[k], s = ss[k];
            if (d >= 0 && d < NN && s >= 0 && s < NN) {
                int p = atomicAdd(&g_cur[d], 1);
                if (p >= 0 && p < TOTE) g_srcs[p] = s;
            }
        }
    }
}

// ============================ GEMM (cp.async double-buffered, f32x2) ============================
// MODE 0: A=ext(x), h->g_hh(fp16), fused alpha.  MODE 1: A=g_t4 (already relu'd by agg1), same.
// MODE 2: A=g_t4, C=ext out, Wn=57, +bias (sync W staging; rows not 16B-aligned).
template <int MODE>
__global__ void __launch_bounds__(256) gemm_kernel(const float4* __restrict__ Aext,
                            const float* __restrict__ W,
                            const float* __restrict__ avs,
                            const float* __restrict__ avd,
                            const float* __restrict__ bias,
                            float* __restrict__ Cext) {
    constexpr int Wn = (MODE == 2) ? DOUT : DH;
    __shared__ float4     As[64 * 32];       // 32 KB A tile
    __shared__ ulonglong2 Ws2[2][32 * 32];   // 2 x 16 KB W quarters

    const float4* A = (MODE == 0) ? Aext : g_t4;

    int tid = threadIdx.x;                   // 256 threads
    int tx = tid & 31, ty = tid >> 5;
    int rowBase = blockIdx.x * 64;
    int rmax = NN - rowBase;

    // ---- prologue: async A tile (+ async W quarter 0 for MODE<2) ----
    for (int i = tid; i < 64 * 32; i += 256) {
        int r = i >> 5;
        if (r < rmax) cp_async16(&As[i], &A[rowBase * 32 + i]);
        else          As[i] = make_float4(0.f, 0.f, 0.f, 0.f);
    }
    if (MODE < 2) {
        const float4* W4 = (const float4*)W;     // Wn=128: quarter = 1024 float4 contiguous
        for (int i = tid; i < 1024; i += 256)
            cp_async16(((float4*)Ws2[0]) + i, W4 + i);
    }
    cp_async_commit();

    unsigned long long accL[8], accH[8];
#pragma unroll
    for (int i = 0; i < 8; ++i) { accL[i] = 0ull; accH[i] = 0ull; }

    for (int q = 0; q < 4; ++q) {
        const ulonglong2* Wb;
        if (MODE < 2) {
            cp_async_wait_all();                 // W(q) + (q==0: A) landed
            __syncthreads();                     // all threads past compute(q-1)
            if (q < 3) {                         // prefetch W(q+1) into alt buffer
                const float4* W4 = (const float4*)W;
                for (int i = tid; i < 1024; i += 256)
                    cp_async16(((float4*)Ws2[(q + 1) & 1]) + i, W4 + (q + 1) * 1024 + i);
                cp_async_commit();
            }
            Wb = Ws2[q & 1];
        } else {
            __syncthreads();                     // Ws reuse
            float* Wsf = (float*)Ws2[0];
            for (int i = tid; i < 32 * DH; i += 256) {
                int k = i >> 7, c = i & 127;
                Wsf[i] = (c < Wn) ? W[(q * 32 + k) * Wn + c] : 0.f;
            }
            if (q == 0) cp_async_wait_all();     // A tile landed
            __syncthreads();
            Wb = Ws2[0];
        }

#pragma unroll 2
        for (int k4 = 0; k4 < 8; ++k4) {
            ulonglong2 w0 = Wb[(k4 * 4 + 0) * 32 + tx];
            ulonglong2 w1 = Wb[(k4 * 4 + 1) * 32 + tx];
            ulonglong2 w2 = Wb[(k4 * 4 + 2) * 32 + tx];
            ulonglong2 w3 = Wb[(k4 * 4 + 3) * 32 + tx];
#pragma unroll
            for (int i = 0; i < 8; ++i) {
                float4 a = As[(ty * 8 + i) * 32 + q * 8 + k4];
                unsigned long long ax = pack2(a.x), ay = pack2(a.y);
                unsigned long long az = pack2(a.z), aw = pack2(a.w);
                fma2(accL[i], ax, w0.x); fma2(accH[i], ax, w0.y);
                fma2(accL[i], ay, w1.x); fma2(accH[i], ay, w1.y);
                fma2(accL[i], az, w2.x); fma2(accH[i], az, w2.y);
                fma2(accL[i], aw, w3.x); fma2(accH[i], aw, w3.y);
            }
        }
    }

    if (MODE < 2) {
        float as0 = avs[4 * tx + 0], as1 = avs[4 * tx + 1], as2 = avs[4 * tx + 2], as3 = avs[4 * tx + 3];
        float ad0 = avd[4 * tx + 0], ad1 = avd[4 * tx + 1], ad2 = avd[4 * tx + 2], ad3 = avd[4 * tx + 3];
#pragma unroll
        for (int i = 0; i < 8; ++i) {
            int row = rowBase + ty * 8 + i;
            float2 lo = unpack2(accL[i]), hi = unpack2(accH[i]);
            float4 acc = make_float4(lo.x, lo.y, hi.x, hi.y);
            float ps = acc.x * as0 + acc.y * as1 + acc.z * as2 + acc.w * as3;
            float pd = acc.x * ad0 + acc.y * ad1 + acc.z * ad2 + acc.w * ad3;
#pragma unroll
            for (int o = 16; o; o >>= 1) {
                ps += __shfl_xor_sync(0xffffffffu, ps, o);
                pd += __shfl_xor_sync(0xffffffffu, pd, o);
            }
            if (row < NN) {
                g_hh[row * 32 + tx] = make_uint2(f2_to_h2(acc.x, acc.y),
                                                 f2_to_h2(acc.z, acc.w));
                if (tx == 0) { g_as[row] = ps; g_ad[row] = pd; }
            }
        }
    } else {
#pragma unroll
        for (int i = 0; i < 8; ++i) {
            int row = rowBase + ty * 8 + i;
            if (row < NN) {
                float2 lo = unpack2(accL[i]), hi = unpack2(accH[i]);
                float v[4] = {lo.x, lo.y, hi.x, hi.y};
#pragma unroll
                for (int j = 0; j < 4; ++j) {
                    int col = 4 * tx + j;
                    if (col < DOUT) Cext[row * DOUT + col] = v[j] + bias[col];
                }
            }
        }
    }
}

// ==================== segment softmax + aggregation (R10 2-way; optional relu-out) ====================
template <bool RELU_OUT>
__global__ void __launch_bounds__(256) agg_kernel(const float* __restrict__ bias) {
    int w = (blockIdx.x * blockDim.x + threadIdx.x) >> 5;
    if (w >= NN) return;
    int lane = threadIdx.x & 31;
    int beg = g_off[w], end = g_off[w + 1];
    float adn = g_ad[w];

    float4 acc0 = make_float4(0.f, 0.f, 0.f, 0.f);
    float4 acc1 = make_float4(0.f, 0.f, 0.f, 0.f);
    float den = 0.f;

    for (int b = beg; b < end; b += 32) {
        int j = b + lane;
        int s = 0; float ex = 0.f;
        if (j < end) {
            s = g_srcs[j];
            float e = g_as[s] + adn;
            e = (e > 0.f) ? e : 0.2f * e;
            ex = __expf(e);
        }
        den += ex;
        int cnt = min(32, end - b);
        int jj = 0;
        for (; jj + 2 <= cnt; jj += 2) {
            int   s0 = __shfl_sync(0xffffffffu, s,  jj);
            int   s1 = __shfl_sync(0xffffffffu, s,  jj + 1);
            float w0 = __shfl_sync(0xffffffffu, ex, jj);
            float w1 = __shfl_sync(0xffffffffu, ex, jj + 1);
            uint2 u0 = g_hh[s0 * 32 + lane];
            uint2 u1 = g_hh[s1 * 32 + lane];
            float2 f0a = h2_to_f2(u0.x), f0b = h2_to_f2(u0.y);
            float2 f1a = h2_to_f2(u1.x), f1b = h2_to_f2(u1.y);
            acc0.x += w0 * f0a.x; acc0.y += w0 * f0a.y; acc0.z += w0 * f0b.x; acc0.w += w0 * f0b.y;
            acc1.x += w1 * f1a.x; acc1.y += w1 * f1a.y; acc1.z += w1 * f1b.x; acc1.w += w1 * f1b.y;
        }
        if (jj < cnt) {
            int   s0 = __shfl_sync(0xffffffffu, s,  jj);
            float w0 = __shfl_sync(0xffffffffu, ex, jj);
            uint2 u0 = g_hh[s0 * 32 + lane];
            float2 f0a = h2_to_f2(u0.x), f0b = h2_to_f2(u0.y);
            acc0.x += w0 * f0a.x; acc0.y += w0 * f0a.y; acc0.z += w0 * f0b.x; acc0.w += w0 * f0b.y;
        }
    }
#pragma unroll
    for (int o = 16; o; o >>= 1) den += __shfl_xor_sync(0xffffffffu, den, o);
    float inv = 1.0f / den;

    float b0 = bias[4 * lane + 0], b1 = bias[4 * lane + 1];
    float b2 = bias[4 * lane + 2], b3 = bias[4 * lane + 3];
    float4 v = make_float4((acc0.x + acc1.x) * inv + b0,
                           (acc0.y + acc1.y) * inv + b1,
                           (acc0.z + acc1.z) * inv + b2,
                           (acc0.w + acc1.w) * inv + b3);
    if (RELU_OUT) {
        v.x = fmaxf(v.x, 0.f); v.y = fmaxf(v.y, 0.f);
        v.z = fmaxf(v.z, 0.f); v.w = fmaxf(v.w, 0.f);
    }
    g_t4[w * 32 + lane] = v;
}

// ============================ launch ============================
extern "C" void kernel_launch(void* const* d_in, const int* in_sizes, int n_in,
                              void* d_out, int out_size) {
    const float* x   = (const float*)d_in[0];
    const int*   ei  = (const int*)d_in[1];     // int32 (JAX x64-disabled)
    const float* W1  = (const float*)d_in[2];
    const float* a1s = (const float*)d_in[3];
    const float* a1d = (const float*)d_in[4];
    const float* b1  = (const float*)d_in[5];
    const float* W2  = (const float*)d_in[6];
    const float* a2s = (const float*)d_in[7];
    const float* a2d = (const float*)d_in[8];
    const float* b2  = (const float*)d_in[9];
    const float* fcw = (const float*)d_in[10];
    const float* fcb = (const float*)d_in[11];
    float*       out = (float*)d_out;
    int E = in_sizes[1] / 2;
    int E4 = (E + 3) / 4;

    int gemm_blocks = (NN + 63) / 64;
    int agg_blocks  = (NN * 32 + 255) / 256;

    k_count<<<(E4 + 255) / 256, 256>>>(ei, E);
    k_scan<<<1, 1024>>>();
    k_scatter<<<(E4 + 255) / 256, 256>>>(ei, E);

    // layer 1 (gemm0 = profiled slot)
    gemm_kernel<0><<<gemm_blocks, 256>>>((const float4*)x, W1, a1s, a1d, nullptr, nullptr);
    agg_kernel<true><<<agg_blocks, 256>>>(b1);   // relu fused into output
    // layer 2 (input already relu'd)
    gemm_kernel<1><<<gemm_blocks, 256>>>(nullptr, W2, a2s, a2d, nullptr, nullptr);
    agg_kernel<false><<<agg_blocks, 256>>>(b2);
    // output head
    gemm_kernel<2><<<gemm_blocks, 256>>>(nullptr, fcw, nullptr, nullptr, fcb, out);
}

// round 14
// speedup vs baseline: 1.7939x; 1.5738x over previous
#include <cuda_runtime.h>
#include <cuda_fp16.h>
#include <math.h>

#define NN   50000
#define DH   128
#define DOUT 57
#define TOTE (800000 + NN)
#define NBLK 49   // ceil(50000/1024)

// -------- scratch (__device__ globals; zero-initialized at load) --------
__device__ uint2  g_hh[NN * 32];   // h in fp16: [N][32] x (2 half2)
__device__ float4 g_t4[NN * 32];   // aggregation output [N,128] fp32
__device__ float  g_as[NN];        // alpha_src per node
__device__ float  g_ad[NN];        // alpha_dst per node
__device__ int    g_deg[NN];       // zero-init; reset to 0 by k_emit each replay
__device__ int    g_off[NN + 1];
__device__ int    g_cur[NN];
__device__ int    g_srcs[TOTE];    // CSR (by dst): src node per edge
__device__ int    g_bsum[NBLK];    // per-block (deg+1) sums

// ---------------- f32x2 packed-FMA helpers (sm_103a) ----------------
__device__ __forceinline__ unsigned long long pack2(float v) {
    unsigned long long r;
    asm("mov.b64 %0, {%1, %1};" : "=l"(r) : "f"(v));
    return r;
}
__device__ __forceinline__ void fma2(unsigned long long& d,
                                     unsigned long long a, unsigned long long b) {
    asm("fma.rn.f32x2 %0, %1, %2, %0;" : "+l"(d) : "l"(a), "l"(b));
}
__device__ __forceinline__ float2 unpack2(unsigned long long v) {
    float x, y;
    asm("mov.b64 {%0, %1}, %2;" : "=f"(x), "=f"(y) : "l"(v));
    return make_float2(x, y);
}

// ---------------- fp16x2 <-> fp32 helpers ----------------
__device__ __forceinline__ unsigned int f2_to_h2(float lo, float hi) {
    unsigned int r;
    asm("cvt.rn.f16x2.f32 %0, %2, %1;" : "=r"(r) : "f"(lo), "f"(hi));
    return r;
}
__device__ __forceinline__ float2 h2_to_f2(unsigned int u) {
    __half2 h = *reinterpret_cast<__half2*>(&u);
    return __half22float2(h);
}

// ---------------- cp.async helpers ----------------
__device__ __forceinline__ void cp_async16(void* smem_dst, const void* gmem_src) {
    unsigned int d = (unsigned int)__cvta_generic_to_shared(smem_dst);
    asm volatile("cp.async.cg.shared.global [%0], [%1], 16;" :: "r"(d), "l"(gmem_src));
}
__device__ __forceinline__ void cp_async_commit() {
    asm volatile("cp.async.commit_group;" ::: "memory");
}
__device__ __forceinline__ void cp_async_wait_all() {
    asm volatile("cp.async.wait_group 0;" ::: "memory");
}

// ============================ CSR build (5 small kernels, all coalesced) ============================
__global__ void k_count(const int* __restrict__ ei, int E) {
    int e4 = blockIdx.x * blockDim.x + threadIdx.x;
    if (e4 * 4 < E) {
        int4 d = ((const int4*)(ei + E))[e4];
        if (d.x >= 0 && d.x < NN) atomicAdd(&g_deg[d.x], 1);
        if (d.y >= 0 && d.y < NN) atomicAdd(&g_deg[d.y], 1);
        if (d.z >= 0 && d.z < NN) atomicAdd(&g_deg[d.z], 1);
        if (d.w >= 0 && d.w < NN) atomicAdd(&g_deg[d.w], 1);
    }
}

// per-1024-chunk sum of (deg+1), coalesced
__global__ void k_blocksum() {
    __shared__ int red[1024];
    int t = threadIdx.x;
    int idx = blockIdx.x * 1024 + t;
    red[t] = (idx < NN) ? (g_deg[idx] + 1) : 0;
    __syncthreads();
    for (int d = 512; d > 0; d >>= 1) {
        if (t < d) red[t] += red[t + d];
        __syncthreads();
    }
    if (t == 0) g_bsum[blockIdx.x] = red[0];
}

// tiny exclusive scan of NBLK block sums (in place -> g_bsum holds exclusive prefix),
// total -> g_off[NN]
__global__ void k_top() {
    if (threadIdx.x == 0) {
        int run = 0;
        for (int b = 0; b < NBLK; ++b) {
            int v = g_bsum[b];
            g_bsum[b] = run;
            run += v;
        }
        g_off[NN] = run;
    }
}

// block-level scan + emit offsets/self-loops/cursors, coalesced (except 1 scattered
// self-loop store per node)
__global__ void k_emit() {
    __shared__ int sc[1024];
    int t = threadIdx.x;
    int idx = blockIdx.x * 1024 + t;
    int v = (idx < NN) ? (g_deg[idx] + 1) : 0;
    sc[t] = v;
    __syncthreads();
    for (int d = 1; d < 1024; d <<= 1) {
        int add = (t >= d) ? sc[t - d] : 0;
        __syncthreads();
        sc[t] += add;
        __syncthreads();
    }
    if (idx < NN) {
        int off = g_bsum[blockIdx.x] + sc[t] - v;   // exclusive prefix
        g_off[idx] = off;
        g_srcs[off] = idx;       // self loop in slot 0
        g_cur[idx] = off + 1;
        g_deg[idx] = 0;          // reset for next replay
    }
}

__global__ void k_scatter(const int* __restrict__ ei, int E) {
    int e4 = blockIdx.x * blockDim.x + threadIdx.x;
    if (e4 * 4 < E) {
        int4 sv = ((const int4*)ei)[e4];
        int4 dv = ((const int4*)(ei + E))[e4];
        int ss[4] = {sv.x, sv.y, sv.z, sv.w};
        int dd[4] = {dv.x, dv.y, dv.z, dv.w};
#pragma unroll
        for (int k = 0; k < 4; ++k) {
            int d = dd[k], s = ss[k];
            if (d >= 0 && d < NN && s >= 0 && s < NN) {
                int p = atomicAdd(&g_cur[d], 1);
                if (p >= 0 && p < TOTE) g_srcs[p] = s;
            }
        }
    }
}

// ============================ GEMM (cp.async double-buffered, f32x2) ============================
template <int MODE>
__global__ void __launch_bounds__(256) gemm_kernel(const float4* __restrict__ Aext,
                            const float* __restrict__ W,
                            const float* __restrict__ avs,
                            const float* __restrict__ avd,
                            const float* __restrict__ bias,
                            float* __restrict__ Cext) {
    constexpr int Wn = (MODE == 2) ? DOUT : DH;
    __shared__ float4     As[64 * 32];       // 32 KB A tile
    __shared__ ulonglong2 Ws2[2][32 * 32];   // 2 x 16 KB W quarters

    const float4* A = (MODE == 0) ? Aext : g_t4;

    int tid = threadIdx.x;                   // 256 threads
    int tx = tid & 31, ty = tid >> 5;
    int rowBase = blockIdx.x * 64;
    int rmax = NN - rowBase;

    for (int i = tid; i < 64 * 32; i += 256) {
        int r = i >> 5;
        if (r < rmax) cp_async16(&As[i], &A[rowBase * 32 + i]);
        else          As[i] = make_float4(0.f, 0.f, 0.f, 0.f);
    }
    if (MODE < 2) {
        const float4* W4 = (const float4*)W;
        for (int i = tid; i < 1024; i += 256)
            cp_async16(((float4*)Ws2[0]) + i, W4 + i);
    }
    cp_async_commit();

    unsigned long long accL[8], accH[8];
#pragma unroll
    for (int i = 0; i < 8; ++i) { accL[i] = 0ull; accH[i] = 0ull; }

    for (int q = 0; q < 4; ++q) {
        const ulonglong2* Wb;
        if (MODE < 2) {
            cp_async_wait_all();
            __syncthreads();
            if (q < 3) {
                const float4* W4 = (const float4*)W;
                for (int i = tid; i < 1024; i += 256)
                    cp_async16(((float4*)Ws2[(q + 1) & 1]) + i, W4 + (q + 1) * 1024 + i);
                cp_async_commit();
            }
            Wb = Ws2[q & 1];
        } else {
            __syncthreads();
            float* Wsf = (float*)Ws2[0];
            for (int i = tid; i < 32 * DH; i += 256) {
                int k = i >> 7, c = i & 127;
                Wsf[i] = (c < Wn) ? W[(q * 32 + k) * Wn + c] : 0.f;
            }
            if (q == 0) cp_async_wait_all();
            __syncthreads();
            Wb = Ws2[0];
        }

#pragma unroll 2
        for (int k4 = 0; k4 < 8; ++k4) {
            ulonglong2 w0 = Wb[(k4 * 4 + 0) * 32 + tx];
            ulonglong2 w1 = Wb[(k4 * 4 + 1) * 32 + tx];
            ulonglong2 w2 = Wb[(k4 * 4 + 2) * 32 + tx];
            ulonglong2 w3 = Wb[(k4 * 4 + 3) * 32 + tx];
#pragma unroll
            for (int i = 0; i < 8; ++i) {
                float4 a = As[(ty * 8 + i) * 32 + q * 8 + k4];
                unsigned long long ax = pack2(a.x), ay = pack2(a.y);
                unsigned long long az = pack2(a.z), aw = pack2(a.w);
                fma2(accL[i], ax, w0.x); fma2(accH[i], ax, w0.y);
                fma2(accL[i], ay, w1.x); fma2(accH[i], ay, w1.y);
                fma2(accL[i], az, w2.x); fma2(accH[i], az, w2.y);
                fma2(accL[i], aw, w3.x); fma2(accH[i], aw, w3.y);
            }
        }
    }

    if (MODE < 2) {
        float as0 = avs[4 * tx + 0], as1 = avs[4 * tx + 1], as2 = avs[4 * tx + 2], as3 = avs[4 * tx + 3];
        float ad0 = avd[4 * tx + 0], ad1 = avd[4 * tx + 1], ad2 = avd[4 * tx + 2], ad3 = avd[4 * tx + 3];
#pragma unroll
        for (int i = 0; i < 8; ++i) {
            int row = rowBase + ty * 8 + i;
            float2 lo = unpack2(accL[i]), hi = unpack2(accH[i]);
            float4 acc = make_float4(lo.x, lo.y, hi.x, hi.y);
            float ps = acc.x * as0 + acc.y * as1 + acc.z * as2 + acc.w * as3;
            float pd = acc.x * ad0 + acc.y * ad1 + acc.z * ad2 + acc.w * ad3;
#pragma unroll
            for (int o = 16; o; o >>= 1) {
                ps += __shfl_xor_sync(0xffffffffu, ps, o);
                pd += __shfl_xor_sync(0xffffffffu, pd, o);
            }
            if (row < NN) {
                g_hh[row * 32 + tx] = make_uint2(f2_to_h2(acc.x, acc.y),
                                                 f2_to_h2(acc.z, acc.w));
                if (tx == 0) { g_as[row] = ps; g_ad[row] = pd; }
            }
        }
    } else {
#pragma unroll
        for (int i = 0; i < 8; ++i) {
            int row = rowBase + ty * 8 + i;
            if (row < NN) {
                float2 lo = unpack2(accL[i]), hi = unpack2(accH[i]);
                float v[4] = {lo.x, lo.y, hi.x, hi.y};
#pragma unroll
                for (int j = 0; j < 4; ++j) {
                    int col = 4 * tx + j;
                    if (col < DOUT) Cext[row * DOUT + col] = v[j] + bias[col];
                }
            }
        }
    }
}

// ==================== segment softmax + aggregation (2-way; optional relu-out) ====================
template <bool RELU_OUT>
__global__ void __launch_bounds__(256) agg_kernel(const float* __restrict__ bias) {
    int w = (blockIdx.x * blockDim.x + threadIdx.x) >> 5;
    if (w >= NN) return;
    int lane = threadIdx.x & 31;
    int beg = g_off[w], end = g_off[w + 1];
    float adn = g_ad[w];

    float4 acc0 = make_float4(0.f, 0.f, 0.f, 0.f);
    float4 acc1 = make_float4(0.f, 0.f, 0.f, 0.f);
    float den = 0.f;

    for (int b = beg; b < end; b += 32) {
        int j = b + lane;
        int s = 0; float ex = 0.f;
        if (j < end) {
            s = g_srcs[j];
            float e = g_as[s] + adn;
            e = (e > 0.f) ? e : 0.2f * e;
            ex = __expf(e);
        }
        den += ex;
        int cnt = min(32, end - b);
        int jj = 0;
        for (; jj + 2 <= cnt; jj += 2) {
            int   s0 = __shfl_sync(0xffffffffu, s,  jj);
            int   s1 = __shfl_sync(0xffffffffu, s,  jj + 1);
            float w0 = __shfl_sync(0xffffffffu, ex, jj);
            float w1 = __shfl_sync(0xffffffffu, ex, jj + 1);
            uint2 u0 = g_hh[s0 * 32 + lane];
            uint2 u1 = g_hh[s1 * 32 + lane];
            float2 f0a = h2_to_f2(u0.x), f0b = h2_to_f2(u0.y);
            float2 f1a = h2_to_f2(u1.x), f1b = h2_to_f2(u1.y);
            acc0.x += w0 * f0a.x; acc0.y += w0 * f0a.y; acc0.z += w0 * f0b.x; acc0.w += w0 * f0b.y;
            acc1.x += w1 * f1a.x; acc1.y += w1 * f1a.y; acc1.z += w1 * f1b.x; acc1.w += w1 * f1b.y;
        }
        if (jj < cnt) {
            int   s0 = __shfl_sync(0xffffffffu, s,  jj);
            float w0 = __shfl_sync(0xffffffffu, ex, jj);
            uint2 u0 = g_hh[s0 * 32 + lane];
            float2 f0a = h2_to_f2(u0.x), f0b = h2_to_f2(u0.y);
            acc0.x += w0 * f0a.x; acc0.y += w0 * f0a.y; acc0.z += w0 * f0b.x; acc0.w += w0 * f0b.y;
        }
    }
#pragma unroll
    for (int o = 16; o; o >>= 1) den += __shfl_xor_sync(0xffffffffu, den, o);
    float inv = 1.0f / den;

    float b0 = bias[4 * lane + 0], b1 = bias[4 * lane + 1];
    float b2 = bias[4 * lane + 2], b3 = bias[4 * lane + 3];
    float4 v = make_float4((acc0.x + acc1.x) * inv + b0,
                           (acc0.y + acc1.y) * inv + b1,
                           (acc0.z + acc1.z) * inv + b2,
                           (acc0.w + acc1.w) * inv + b3);
    if (RELU_OUT) {
        v.x = fmaxf(v.x, 0.f); v.y = fmaxf(v.y, 0.f);
        v.z = fmaxf(v.z, 0.f); v.w = fmaxf(v.w, 0.f);
    }
    g_t4[w * 32 + lane] = v;
}

// ============================ launch ============================
extern "C" void kernel_launch(void* const* d_in, const int* in_sizes, int n_in,
                              void* d_out, int out_size) {
    const float* x   = (const float*)d_in[0];
    const int*   ei  = (const int*)d_in[1];     // int32 (JAX x64-disabled)
    const float* W1  = (const float*)d_in[2];
    const float* a1s = (const float*)d_in[3];
    const float* a1d = (const float*)d_in[4];
    const float* b1  = (const float*)d_in[5];
    const float* W2  = (const float*)d_in[6];
    const float* a2s = (const float*)d_in[7];
    const float* a2d = (const float*)d_in[8];
    const float* b2  = (const float*)d_in[9];
    const float* fcw = (const float*)d_in[10];
    const float* fcb = (const float*)d_in[11];
    float*       out = (float*)d_out;
    int E = in_sizes[1] / 2;
    int E4 = (E + 3) / 4;

    int gemm_blocks = (NN + 63) / 64;
    int agg_blocks  = (NN * 32 + 255) / 256;

    // CSR build (parallel scan)
    k_count<<<(E4 + 255) / 256, 256>>>(ei, E);
    k_blocksum<<<NBLK, 1024>>>();
    k_top<<<1, 32>>>();
    k_emit<<<NBLK, 1024>>>();
    k_scatter<<<(E4 + 255) / 256, 256>>>(ei, E);

    // layer 1
    gemm_kernel<0><<<gemm_blocks, 256>>>((const float4*)x, W1, a1s, a1d, nullptr, nullptr);
    agg_kernel<true><<<agg_blocks, 256>>>(b1);   // relu fused into output
    // layer 2 (input already relu'd)
    gemm_kernel<1><<<gemm_blocks, 256>>>(nullptr, W2, a2s, a2d, nullptr, nullptr);
    agg_kernel<false><<<agg_blocks, 256>>>(b2);
    // output head
    gemm_kernel<2><<<gemm_blocks, 256>>>(nullptr, fcw, nullptr, nullptr, fcb, out);
}